// round 15
// baseline (speedup 1.0000x reference)
#include <cuda_runtime.h>
#include <math.h>

#define LOG2E 1.4426950408889634f

typedef unsigned long long u64p;             // packed f32x2

// ---- device-global intermediates (allocation-free scratch) ----
__device__ float g_S [128 * 2560];           // S[b][c][o][q]  (route output)
__device__ float g_Wv[128 * 2560];           // accumulated Wv[b][c][o][q], log2e-scaled

__device__ __forceinline__ u64p pk2(float lo, float hi) {
    u64p r; asm("mov.b64 %0, {%1, %2};" : "=l"(r) : "f"(lo), "f"(hi)); return r;
}
__device__ __forceinline__ void upk2(u64p v, float& lo, float& hi) {
    asm("mov.b64 {%0, %1}, %2;" : "=f"(lo), "=f"(hi) : "l"(v));
}
__device__ __forceinline__ float ex2f(float x) {
    float y; asm("ex2.approx.ftz.f32 %0, %1;" : "=f"(y) : "f"(x)); return y;
}
#define FMA2(d, a, b, c) asm("fma.rn.f32x2 %0, %1, %2, %3;" : "=l"(d) : "l"(a), "l"(b), "l"(c))
#define MUL2(d, a, b)    asm("mul.rn.f32x2 %0, %1, %2;"      : "=l"(d) : "l"(a), "l"(b))

// ---------------------------------------------------------------------------
// contract + squash (warp w<10 owns o=w). S_s layout: PER_O ? c*80+o*8 : c*8.
// out_v: LAST -> squashed v (final output values); else log2e-scaled v for Wv.
// ---------------------------------------------------------------------------
template <bool PER_O, bool LAST>
__device__ __forceinline__ void contract_v(const float* __restrict__ Wg,
                                           const float* __restrict__ S_s,
                                           float* __restrict__ out_v,
                                           int w, int lane)
{
    if (w < 10) {
        const int o = w;
        const int p = lane & 15;
        const int h = lane >> 4;
        const float* wbase = Wg + o * 128 + p * 8 + h * 4;
        float a0 = 0.f, a1 = 0.f, a2 = 0.f, a3 = 0.f;
#pragma unroll 16
        for (int c = 0; c < 32; ++c) {
            const float4 w4 = *reinterpret_cast<const float4*>(wbase + c * 1280);
            const float4 s4 = *reinterpret_cast<const float4*>(
                S_s + (PER_O ? (c * 80 + o * 8 + h * 4) : (c * 8 + h * 4)));
            a0 += w4.x * s4.x; a1 += w4.y * s4.y;
            a2 += w4.z * s4.z; a3 += w4.w * s4.w;
        }
        float s = (a0 + a1) + (a2 + a3);
        s += __shfl_xor_sync(0xffffffffu, s, 16);     // combine q-halves

        float sq = s * s;
        sq += __shfl_xor_sync(0xffffffffu, sq, 1);
        sq += __shfl_xor_sync(0xffffffffu, sq, 2);
        sq += __shfl_xor_sync(0xffffffffu, sq, 4);
        sq += __shfl_xor_sync(0xffffffffu, sq, 8);    // ||s||^2 over 16 p-lanes

        const float mult = LAST ? 1.f : LOG2E;
        const float sc = __fdividef(__fsqrt_rn(sq) * mult, 1.f + sq);
        if (h == 0) out_v[o * 16 + p] = s * sc;
    }
}

// ---------------------------------------------------------------------------
// Warp-cooperative Wv into GMEM: 16 warps x 20 (c,o) pairs, coalesced W reads,
// compile-time (c,o) decomposition (no runtime int division).
// ---------------------------------------------------------------------------
template <bool ACC>
__device__ __forceinline__ void compute_Wv(const float* __restrict__ Wg,
                                           const float* __restrict__ v_b,
                                           float* __restrict__ wv_dst,
                                           int w, int lane)
{
    const int q   = lane & 7;
    const int pg  = lane >> 3;
    const int c0  = w * 2;
    const float* wbase = Wg + c0 * 1280;
    float* dbase = wv_dst + c0 * 80;
#pragma unroll
    for (int m = 0; m < 20; ++m) {
        const int dc = (m >= 10) ? 1 : 0;
        const int o  = m - 10 * dc;
        const float* wrow = wbase + dc * 1280 + o * 128;
        const float* vrow = v_b + o * 16 + pg;
        float acc = wrow[lane]       * vrow[0]
                  + wrow[32 + lane]  * vrow[4]
                  + wrow[64 + lane]  * vrow[8]
                  + wrow[96 + lane]  * vrow[12];
        acc += __shfl_xor_sync(0xffffffffu, acc, 8);
        acc += __shfl_xor_sync(0xffffffffu, acc, 16);
        if (lane < 8) {
            float* d = dbase + dc * 80 + o * 8 + q;
            *d = ACC ? (*d + acc) : acc;
        }
    }
}

// ---------------------------------------------------------------------------
// K1: iteration 0 (c_ij = 1/10) + contract + squash + Wv(v0). Grid = 128 (b).
// No SMEM staging of u — sums accumulate in-flight from GMEM.
// ---------------------------------------------------------------------------
__global__ __launch_bounds__(512, 1)
void k_init(const float* __restrict__ xg, const float* __restrict__ Wg)
{
    __shared__ __align__(16) float S0[256];   // [32][8]
    __shared__ float v_b[160];
    const int b = blockIdx.x, tid = threadIdx.x;
    const int w = tid >> 5, lane = tid & 31;

#pragma unroll
    for (int ci = 0; ci < 2; ++ci) {
        const int c = w + 16 * ci;
        const float4* src =
            reinterpret_cast<const float4*>(xg + (size_t)b * 36864 + c * 1152);
        float4 acc = make_float4(0.f, 0.f, 0.f, 0.f);
#pragma unroll
        for (int k = 0; k < 9; ++k) {
            float4 t = src[lane + 32 * k];
            acc.x += t.x; acc.y += t.y; acc.z += t.z; acc.w += t.w;
        }
#pragma unroll
        for (int msk = 2; msk <= 16; msk <<= 1) {
            acc.x += __shfl_xor_sync(0xffffffffu, acc.x, msk);
            acc.y += __shfl_xor_sync(0xffffffffu, acc.y, msk);
            acc.z += __shfl_xor_sync(0xffffffffu, acc.z, msk);
            acc.w += __shfl_xor_sync(0xffffffffu, acc.w, msk);
        }
        if (lane < 2) {    // lane0 -> q0-3, lane1 -> q4-7 (float4 parity = lane parity)
            float4* so = reinterpret_cast<float4*>(S0 + c * 8 + lane * 4);
            so[0] = make_float4(acc.x * 0.1f, acc.y * 0.1f, acc.z * 0.1f, acc.w * 0.1f);
        }
    }
    __syncthreads();
    contract_v<false, false>(Wg, S0, v_b, w, lane);
    __syncthreads();
    compute_Wv<false>(Wg, v_b, g_Wv + b * 2560, w, lane);
}

// ---------------------------------------------------------------------------
// K_route: one routing iteration for ONE (b, c). Grid = (32, 128), 128 threads.
// Warp w handles 36 points: l16 covers points w*36+l16, +16, +32 (last only
// l16<4 — zero-filled u contributes exactly 0 to S, so no predication needed
// past the load). Lanes 0-15: o 0-4, lanes 16-31: o 5-9 (o-split + shfl 16).
// wv slice (log2e-scaled) hoisted to registers; three independent softmax
// chains per lane give the ILP that the monolithic kernel couldn't afford.
// ---------------------------------------------------------------------------
__global__ __launch_bounds__(128, 4)
void k_route(const float* __restrict__ xg)
{
    __shared__ float part[320];                // [warp][80]
    const int c = blockIdx.x, b = blockIdx.y;
    const int tid = threadIdx.x;
    const int w = tid >> 5, lane = tid & 31, l16 = lane & 15, half = lane >> 4;

    const ulonglong2* wvg = reinterpret_cast<const ulonglong2*>(
        g_Wv + b * 2560 + c * 80 + half * 40);
    u64p wv[20];
#pragma unroll
    for (int z = 0; z < 10; ++z) { ulonglong2 t = wvg[z]; wv[2*z] = t.x; wv[2*z+1] = t.y; }

    const float* ub = xg + (size_t)b * 36864 + c * 1152;
    const int p0 = w * 36 + l16;
    const ulonglong2* u0p = reinterpret_cast<const ulonglong2*>(ub + p0 * 8);

    const ulonglong2 a01 = u0p[0],  a23 = u0p[1];    // point p0
    const ulonglong2 b01 = u0p[32], b23 = u0p[33];   // point p0+16
    ulonglong2 c01 = make_ulonglong2(0ULL, 0ULL);
    ulonglong2 c23 = make_ulonglong2(0ULL, 0ULL);
    if (l16 < 4) { c01 = u0p[64]; c23 = u0p[65]; }   // point p0+32 (tail)

    u64p Sp[20];
#pragma unroll
    for (int z = 0; z < 20; ++z) Sp[z] = 0ULL;

    float exa[5], exb[5], exc[5];
#pragma unroll
    for (int o = 0; o < 5; ++o) {
        u64p ta, tb, tc;
        MUL2(ta, a01.x, wv[4*o]);        MUL2(tb, b01.x, wv[4*o]);        MUL2(tc, c01.x, wv[4*o]);
        FMA2(ta, a01.y, wv[4*o+1], ta);  FMA2(tb, b01.y, wv[4*o+1], tb);  FMA2(tc, c01.y, wv[4*o+1], tc);
        FMA2(ta, a23.x, wv[4*o+2], ta);  FMA2(tb, b23.x, wv[4*o+2], tb);  FMA2(tc, c23.x, wv[4*o+2], tc);
        FMA2(ta, a23.y, wv[4*o+3], ta);  FMA2(tb, b23.y, wv[4*o+3], tb);  FMA2(tc, c23.y, wv[4*o+3], tc);
        float lo, hi;
        upk2(ta, lo, hi); exa[o] = ex2f(lo + hi);
        upk2(tb, lo, hi); exb[o] = ex2f(lo + hi);
        upk2(tc, lo, hi); exc[o] = ex2f(lo + hi);
    }
    const float sa = ((exa[0] + exa[1]) + (exa[2] + exa[3])) + exa[4];
    const float sb = ((exb[0] + exb[1]) + (exb[2] + exb[3])) + exb[4];
    const float sc = ((exc[0] + exc[1]) + (exc[2] + exc[3])) + exc[4];
    const float ra = __fdividef(1.f, sa + __shfl_xor_sync(0xffffffffu, sa, 16));
    const float rb = __fdividef(1.f, sb + __shfl_xor_sync(0xffffffffu, sb, 16));
    const float rc = __fdividef(1.f, sc + __shfl_xor_sync(0xffffffffu, sc, 16));

#pragma unroll
    for (int o = 0; o < 5; ++o) {
        const float cea = exa[o] * ra;
        const float ceb = exb[o] * rb;
        const float cec = exc[o] * rc;
        const u64p pa = pk2(cea, cea), pb = pk2(ceb, ceb), pc = pk2(cec, cec);
        FMA2(Sp[4*o+0], pa, a01.x, Sp[4*o+0]);
        FMA2(Sp[4*o+1], pa, a01.y, Sp[4*o+1]);
        FMA2(Sp[4*o+2], pa, a23.x, Sp[4*o+2]);
        FMA2(Sp[4*o+3], pa, a23.y, Sp[4*o+3]);
        FMA2(Sp[4*o+0], pb, b01.x, Sp[4*o+0]);
        FMA2(Sp[4*o+1], pb, b01.y, Sp[4*o+1]);
        FMA2(Sp[4*o+2], pb, b23.x, Sp[4*o+2]);
        FMA2(Sp[4*o+3], pb, b23.y, Sp[4*o+3]);
        FMA2(Sp[4*o+0], pc, c01.x, Sp[4*o+0]);   // u=0 for l16>=4 -> adds 0
        FMA2(Sp[4*o+1], pc, c01.y, Sp[4*o+1]);
        FMA2(Sp[4*o+2], pc, c23.x, Sp[4*o+2]);
        FMA2(Sp[4*o+3], pc, c23.y, Sp[4*o+3]);
    }

    // split-butterfly reduce 40 values over the 16 l16 lanes
    float v[40];
#pragma unroll
    for (int z = 0; z < 20; ++z) upk2(Sp[z], v[2*z], v[2*z+1]);

    int base = 0;
    {
        const bool up = (l16 & 1);
#pragma unroll
        for (int z = 0; z < 20; ++z) {
            float keep = up ? v[20 + z] : v[z];
            float give = up ? v[z] : v[20 + z];
            v[z] = keep + __shfl_xor_sync(0xffffffffu, give, 1);
        }
        if (up) base += 20;
    }
    {
        const bool up = (l16 & 2);
#pragma unroll
        for (int z = 0; z < 10; ++z) {
            float keep = up ? v[10 + z] : v[z];
            float give = up ? v[z] : v[10 + z];
            v[z] = keep + __shfl_xor_sync(0xffffffffu, give, 2);
        }
        if (up) base += 10;
    }
    {
        const bool up = (l16 & 4);
#pragma unroll
        for (int z = 0; z < 5; ++z) {
            float keep = up ? v[5 + z] : v[z];
            float give = up ? v[z] : v[5 + z];
            v[z] = keep + __shfl_xor_sync(0xffffffffu, give, 4);
        }
        if (up) base += 5;
    }
#pragma unroll
    for (int z = 0; z < 5; ++z)
        v[z] += __shfl_xor_sync(0xffffffffu, v[z], 8);

    if ((l16 & 8) == 0) {
        float* dst = part + w * 80 + half * 40 + base;
#pragma unroll
        for (int z = 0; z < 5; ++z) dst[z] = v[z];
    }
    __syncthreads();

    // sum the 4 warp partials, write S[b][c]
    if (tid < 80) {
        const float s = (part[tid] + part[80 + tid]) + (part[160 + tid] + part[240 + tid]);
        g_S[b * 2560 + c * 80 + tid] = s;
    }
}

// ---------------------------------------------------------------------------
// K_update: contract + squash (+ Wv accumulate, or final output). Grid = 128.
// ---------------------------------------------------------------------------
template <bool LAST>
__global__ __launch_bounds__(512, 1)
void k_update(const float* __restrict__ Wg, float* __restrict__ outg)
{
    __shared__ __align__(16) float S_sm[2560];
    __shared__ float v_b[160];
    const int b = blockIdx.x, tid = threadIdx.x;
    const int w = tid >> 5, lane = tid & 31;

    const float* src = g_S + b * 2560;
#pragma unroll
    for (int i = 0; i < 5; ++i) S_sm[tid + i * 512] = src[tid + i * 512];
    __syncthreads();

    contract_v<true, LAST>(Wg, S_sm, v_b, w, lane);
    __syncthreads();

    if (LAST) {
        if (tid < 160) outg[b * 160 + tid] = v_b[tid];
    } else {
        compute_Wv<true>(Wg, v_b, g_Wv + b * 2560, w, lane);
    }
}

extern "C" void kernel_launch(void* const* d_in, const int* in_sizes, int n_in,
                              void* d_out, int out_size)
{
    const float* x = (const float*)d_in[0];
    const float* W = (const float*)d_in[1];
    if (n_in >= 2 && in_sizes[0] < in_sizes[1]) {
        const float* t = x; x = W; W = t;
    }
    float* out = (float*)d_out;
    (void)out_size;

    const dim3 route_grid(32, 128);

    k_init<<<128, 512>>>(x, W);                 // iter0 + Wv(v0)
    k_route<<<route_grid, 128>>>(x);            // iter1 route
    k_update<false><<<128, 512>>>(W, out);      // iter1 contract + Wv accumulate
    k_route<<<route_grid, 128>>>(x);            // iter2 route
    k_update<true><<<128, 512>>>(W, out);       // iter2 contract + final output
}